// round 1
// baseline (speedup 1.0000x reference)
#include <cuda_runtime.h>
#include <cstdint>
#include <math.h>

// ---------------------------------------------------------------------------
// RelNet forward, fp32 everywhere.
// img[512,3,80,80] -> 4x (conv3x3 s2 p1 + bias + relu + trainBN) -> [512,24,5,5]
// g1 decomposed: h1 = relu(Wi*obj_i + Wj*obj_j + Wq*q + b1)
// g2..g4: 320000x256x256 GEMM + bias + relu
// pairsum -> f1,fc2 (256x256 GEMM+relu) -> fc3(10) -> log_softmax
// ---------------------------------------------------------------------------

#define BATCH 512
#define FS 24
#define OBJ 25
#define HID 256
#define NPAIR (BATCH * OBJ * OBJ)   // 320000

// ------------------------- scratch (static device) -------------------------
__device__ float g_c1[BATCH * FS * 40 * 40];   // 19.66M
__device__ float g_c2[BATCH * FS * 20 * 20];   //  4.92M
__device__ float g_c3[BATCH * FS * 10 * 10];   //  1.23M
__device__ float g_c4[BATCH * FS * 5 * 5];     //  0.31M
__device__ float g_stats[48];                  // per-channel sum / sumsq
__device__ float g_P[BATCH * OBJ * HID];       // Wi proj
__device__ float g_Q[BATCH * OBJ * HID];       // Wj proj
__device__ float g_R[BATCH * HID];             // Wq*q + b1
__device__ float g_hA[(size_t)NPAIR * HID];    // 327MB ping
__device__ float g_hB[(size_t)NPAIR * HID];    // 327MB pong
__device__ float g_xg[BATCH * HID];
__device__ float g_xf1[BATCH * HID];
__device__ float g_xf2[BATCH * HID];

// ------------------------------ conv + relu --------------------------------
__global__ void k_conv(const float* __restrict__ in, const float* __restrict__ w,
                       const float* __restrict__ bias, float* __restrict__ out,
                       int Cin, int Hin, int Win, int Hout, int Wout)
{
    int idx = blockIdx.x * blockDim.x + threadIdx.x;
    int total = BATCH * FS * Hout * Wout;
    if (idx >= total) return;
    int ow = idx % Wout; int t = idx / Wout;
    int oh = t % Hout;   t /= Hout;
    int co = t % FS;     int n = t / FS;

    float s = bias[co];
    const float* wbase = w + co * Cin * 9;
    const float* ibase = in + (size_t)n * Cin * Hin * Win;
    int ih0 = oh * 2 - 1, iw0 = ow * 2 - 1;
    for (int ci = 0; ci < Cin; ci++) {
        const float* ip = ibase + (size_t)ci * Hin * Win;
        const float* wp = wbase + ci * 9;
        #pragma unroll
        for (int kh = 0; kh < 3; kh++) {
            int ih = ih0 + kh;
            if (ih < 0 || ih >= Hin) continue;
            #pragma unroll
            for (int kw = 0; kw < 3; kw++) {
                int iw = iw0 + kw;
                if (iw < 0 || iw >= Win) continue;
                s += ip[ih * Win + iw] * wp[kh * 3 + kw];
            }
        }
    }
    out[idx] = fmaxf(s, 0.0f);
}

// ------------------------------ batchnorm ----------------------------------
__global__ void k_zero48(float* s) { if (threadIdx.x < 48) s[threadIdx.x] = 0.0f; }

__global__ void k_bnstats(const float* __restrict__ y, float* __restrict__ stats, int HW)
{
    int c = blockIdx.x;                 // channel
    int per = BATCH * HW;
    float s = 0.f, s2 = 0.f;
    for (int i = blockIdx.y * blockDim.x + threadIdx.x; i < per;
         i += gridDim.y * blockDim.x) {
        int n = i / HW, hw = i - n * HW;
        float v = y[((size_t)n * FS + c) * HW + hw];
        s += v; s2 += v * v;
    }
    __shared__ float ss[256], ss2[256];
    int tid = threadIdx.x;
    ss[tid] = s; ss2[tid] = s2;
    __syncthreads();
    for (int off = 128; off > 0; off >>= 1) {
        if (tid < off) { ss[tid] += ss[tid + off]; ss2[tid] += ss2[tid + off]; }
        __syncthreads();
    }
    if (tid == 0) {
        atomicAdd(&stats[c], ss[0]);
        atomicAdd(&stats[FS + c], ss2[0]);
    }
}

__global__ void k_bnapply(float* __restrict__ y, const float* __restrict__ stats,
                          const float* __restrict__ gamma, const float* __restrict__ beta,
                          int HW, int total)
{
    int idx = blockIdx.x * blockDim.x + threadIdx.x;
    if (idx >= total) return;
    int c = (idx / HW) % FS;
    float cnt = (float)(BATCH * HW);
    float mean = stats[c] / cnt;
    float var = stats[FS + c] / cnt - mean * mean;
    float inv = gamma[c] * rsqrtf(var + 1e-5f);
    y[idx] = (y[idx] - mean) * inv + beta[c];
}

// ------------------- g1 decomposition: projections + fuse ------------------
// P[b,o,j] = sum_c Wi[j,c]*feat(b,o,c);  Q likewise with Wj (cols 26..51)
__global__ void k_objproj(const float* __restrict__ x4, const float* __restrict__ g1w,
                          float* __restrict__ P, float* __restrict__ Q)
{
    int bo = blockIdx.x;              // 0..12799
    int b = bo / OBJ, o = bo - b * OBJ;
    __shared__ float feat[26];
    int j = threadIdx.x;
    if (j < FS) feat[j] = x4[((size_t)b * FS + j) * OBJ + o];
    if (j == 24) feat[24] = ((o / 5) - 2) * 0.5f;
    if (j == 25) feat[25] = ((o % 5) - 2) * 0.5f;
    __syncthreads();
    const float* wr = g1w + j * 63;
    float p = 0.f, q = 0.f;
    #pragma unroll
    for (int c = 0; c < 26; c++) {
        p += wr[c] * feat[c];
        q += wr[26 + c] * feat[c];
    }
    P[(size_t)bo * HID + j] = p;
    Q[(size_t)bo * HID + j] = q;
}

__global__ void k_qproj(const float* __restrict__ qst, const float* __restrict__ g1w,
                        const float* __restrict__ g1b, float* __restrict__ R)
{
    int b = blockIdx.x, j = threadIdx.x;
    __shared__ float qs[11];
    if (j < 11) qs[j] = qst[j * BATCH + b];
    __syncthreads();
    float s = g1b[j];
    const float* wr = g1w + j * 63 + 52;
    #pragma unroll
    for (int t = 0; t < 11; t++) s += wr[t] * qs[t];
    R[b * HID + j] = s;
}

// h1[row=b*625+a*25+c, j] = relu(P[b,c,j] + Q[b,a,j] + R[b,j])
__global__ void k_g1(const float* __restrict__ P, const float* __restrict__ Q,
                     const float* __restrict__ R, float* __restrict__ h)
{
    int row = blockIdx.x;
    int b = row / 625;
    int rem = row - b * 625;
    int a = rem / OBJ;
    int c = rem - a * OBJ;
    int j = threadIdx.x;
    float v = P[((size_t)b * OBJ + c) * HID + j]
            + Q[((size_t)b * OBJ + a) * HID + j]
            + R[b * HID + j];
    h[(size_t)row * HID + j] = fmaxf(v, 0.0f);
}

// ------------------- GEMM: C = [relu](A[M,256] @ W[256,256]^T + b) ---------
// 128x128 tile, BK=8, 8x8 per thread, 256 threads.
__global__ __launch_bounds__(256) void k_gemm256(const float* __restrict__ A,
    const float* __restrict__ W, const float* __restrict__ bias,
    float* __restrict__ C, int M, int doRelu)
{
    __shared__ float As[8][128];
    __shared__ float Bs[8][128];
    const int tid = threadIdx.x;
    const int bm = blockIdx.x * 128;
    const int bn = blockIdx.y * 128;
    const int tx = tid & 15;
    const int ty = tid >> 4;

    float acc[8][8];
    #pragma unroll
    for (int i = 0; i < 8; i++)
        #pragma unroll
        for (int j = 0; j < 8; j++) acc[i][j] = 0.f;

    const int lrow = tid >> 1;
    const int lk = (tid & 1) * 4;
    const float* Ag = A + (size_t)(bm + lrow) * 256 + lk;
    const float* Wg = W + (size_t)(bn + lrow) * 256 + lk;

    for (int k0 = 0; k0 < 256; k0 += 8) {
        float4 av = *reinterpret_cast<const float4*>(Ag + k0);
        float4 wv = *reinterpret_cast<const float4*>(Wg + k0);
        As[lk + 0][lrow] = av.x; As[lk + 1][lrow] = av.y;
        As[lk + 2][lrow] = av.z; As[lk + 3][lrow] = av.w;
        Bs[lk + 0][lrow] = wv.x; Bs[lk + 1][lrow] = wv.y;
        Bs[lk + 2][lrow] = wv.z; Bs[lk + 3][lrow] = wv.w;
        __syncthreads();
        #pragma unroll
        for (int kk = 0; kk < 8; kk++) {
            float a[8], b[8];
            *reinterpret_cast<float4*>(&a[0]) = *reinterpret_cast<const float4*>(&As[kk][ty * 8]);
            *reinterpret_cast<float4*>(&a[4]) = *reinterpret_cast<const float4*>(&As[kk][ty * 8 + 4]);
            *reinterpret_cast<float4*>(&b[0]) = *reinterpret_cast<const float4*>(&Bs[kk][tx * 8]);
            *reinterpret_cast<float4*>(&b[4]) = *reinterpret_cast<const float4*>(&Bs[kk][tx * 8 + 4]);
            #pragma unroll
            for (int i = 0; i < 8; i++)
                #pragma unroll
                for (int j = 0; j < 8; j++)
                    acc[i][j] += a[i] * b[j];
        }
        __syncthreads();
    }

    #pragma unroll
    for (int i = 0; i < 8; i++) {
        size_t row = (size_t)(bm + ty * 8 + i);
        #pragma unroll
        for (int j = 0; j < 8; j += 4) {
            int col = bn + tx * 8 + j;
            float4 v;
            v.x = acc[i][j + 0] + bias[col + 0];
            v.y = acc[i][j + 1] + bias[col + 1];
            v.z = acc[i][j + 2] + bias[col + 2];
            v.w = acc[i][j + 3] + bias[col + 3];
            if (doRelu) {
                v.x = fmaxf(v.x, 0.f); v.y = fmaxf(v.y, 0.f);
                v.z = fmaxf(v.z, 0.f); v.w = fmaxf(v.w, 0.f);
            }
            *reinterpret_cast<float4*>(&C[row * 256 + col]) = v;
        }
    }
}

// ---------------------------- pair sum -------------------------------------
__global__ void k_pairsum(const float* __restrict__ h, float* __restrict__ xg)
{
    int b = blockIdx.x, j = threadIdx.x;
    const float* base = h + (size_t)b * 625 * HID + j;
    float s0 = 0, s1 = 0, s2 = 0, s3 = 0;
    int p = 0;
    for (; p + 4 <= 624; p += 4) {
        s0 += base[(size_t)(p + 0) * HID];
        s1 += base[(size_t)(p + 1) * HID];
        s2 += base[(size_t)(p + 2) * HID];
        s3 += base[(size_t)(p + 3) * HID];
    }
    float s = s0 + s1 + s2 + s3;
    for (; p < 625; p++) s += base[(size_t)p * HID];
    xg[b * HID + j] = s;
}

// -------------------- fc3 (256->10) + log_softmax --------------------------
__global__ void k_final(const float* __restrict__ xf, const float* __restrict__ w,
                        const float* __restrict__ bias, float* __restrict__ out)
{
    int b = blockIdx.x;
    __shared__ float xs[HID];
    __shared__ float logits[10];
    xs[threadIdx.x] = xf[b * HID + threadIdx.x];
    __syncthreads();
    if (threadIdx.x < 10) {
        float s = bias[threadIdx.x];
        const float* wr = w + threadIdx.x * HID;
        for (int c = 0; c < HID; c++) s += wr[c] * xs[c];
        logits[threadIdx.x] = s;
    }
    __syncthreads();
    if (threadIdx.x == 0) {
        float mx = -1e30f;
        for (int n = 0; n < 10; n++) mx = fmaxf(mx, logits[n]);
        float se = 0.f;
        for (int n = 0; n < 10; n++) se += expf(logits[n] - mx);
        float lse = logf(se) + mx;
        for (int n = 0; n < 10; n++) out[b * 10 + n] = logits[n] - lse;
    }
}

// ---------------------------------------------------------------------------
static void* sym(const void* devSymbol)
{
    void* p = nullptr;
    cudaGetSymbolAddress(&p, devSymbol);
    return p;
}

extern "C" void kernel_launch(void* const* d_in, const int* in_sizes, int n_in,
                              void* d_out, int out_size)
{
    const float* img  = (const float*)d_in[0];
    const float* qst  = (const float*)d_in[1];
    const float* cw[4] = { (const float*)d_in[2],  (const float*)d_in[6],
                           (const float*)d_in[10], (const float*)d_in[14] };
    const float* cb[4] = { (const float*)d_in[3],  (const float*)d_in[7],
                           (const float*)d_in[11], (const float*)d_in[15] };
    const float* bg[4] = { (const float*)d_in[4],  (const float*)d_in[8],
                           (const float*)d_in[12], (const float*)d_in[16] };
    const float* bb[4] = { (const float*)d_in[5],  (const float*)d_in[9],
                           (const float*)d_in[13], (const float*)d_in[17] };
    const float* g1w = (const float*)d_in[18]; const float* g1b = (const float*)d_in[19];
    const float* g2w = (const float*)d_in[20]; const float* g2b = (const float*)d_in[21];
    const float* g3w = (const float*)d_in[22]; const float* g3b = (const float*)d_in[23];
    const float* g4w = (const float*)d_in[24]; const float* g4b = (const float*)d_in[25];
    const float* f1w = (const float*)d_in[26]; const float* f1b = (const float*)d_in[27];
    const float* fc2w = (const float*)d_in[28]; const float* fc2b = (const float*)d_in[29];
    const float* fc3w = (const float*)d_in[30]; const float* fc3b = (const float*)d_in[31];

    float* c1 = (float*)sym(g_c1); float* c2 = (float*)sym(g_c2);
    float* c3 = (float*)sym(g_c3); float* c4 = (float*)sym(g_c4);
    float* stats = (float*)sym(g_stats);
    float* P = (float*)sym(g_P); float* Q = (float*)sym(g_Q); float* R = (float*)sym(g_R);
    float* hA = (float*)sym(g_hA); float* hB = (float*)sym(g_hB);
    float* xg = (float*)sym(g_xg); float* xf1 = (float*)sym(g_xf1); float* xf2 = (float*)sym(g_xf2);
    float* out = (float*)d_out;

    struct { const float* in; float* out; int Cin, Hin, Hout; } L[4] = {
        { img, c1, 3, 80, 40 },
        { c1,  c2, FS, 40, 20 },
        { c2,  c3, FS, 20, 10 },
        { c3,  c4, FS, 10, 5 },
    };

    for (int l = 0; l < 4; l++) {
        int Hout = L[l].Hout, HW = Hout * Hout;
        int total = BATCH * FS * HW;
        k_conv<<<(total + 255) / 256, 256>>>(L[l].in, cw[l], cb[l], L[l].out,
                                             L[l].Cin, L[l].Hin, L[l].Hin, Hout, Hout);
        k_zero48<<<1, 64>>>(stats);
        k_bnstats<<<dim3(FS, 64), 256>>>(L[l].out, stats, HW);
        k_bnapply<<<(total + 255) / 256, 256>>>(L[l].out, stats, bg[l], bb[l], HW, total);
    }

    // g1 decomposition
    k_objproj<<<BATCH * OBJ, HID>>>(c4, g1w, P, Q);
    k_qproj<<<BATCH, HID>>>(qst, g1w, g1b, R);
    k_g1<<<NPAIR, HID>>>(P, Q, R, hA);

    // g2..g4 big GEMMs
    dim3 gbig(NPAIR / 128, 2);
    k_gemm256<<<gbig, 256>>>(hA, g2w, g2b, hB, NPAIR, 1);
    k_gemm256<<<gbig, 256>>>(hB, g3w, g3b, hA, NPAIR, 1);
    k_gemm256<<<gbig, 256>>>(hA, g4w, g4b, hB, NPAIR, 1);

    // sum over 625 pairs
    k_pairsum<<<BATCH, HID>>>(hB, xg);

    // f layers
    dim3 gsmall(BATCH / 128, 2);
    k_gemm256<<<gsmall, 256>>>(xg, f1w, f1b, xf1, BATCH, 1);
    k_gemm256<<<gsmall, 256>>>(xf1, fc2w, fc2b, xf2, BATCH, 1);

    // fc3 + log_softmax
    k_final<<<BATCH, HID>>>(xf2, fc3w, fc3b, out);
}

// round 6
// speedup vs baseline: 2.1491x; 2.1491x over previous
#include <cuda_runtime.h>
#include <cuda_fp16.h>
#include <cstdint>
#include <math.h>

// ---------------------------------------------------------------------------
// RelNet forward.
// conv stack fp32 -> g1 decomposition (fp32 math, fp16 out) ->
// g2..g4: mma.sync fp16 HMMA GEMM, M=320000, N=256, K=256, fp32 accum
//         (g4 writes fp32) -> pairsum -> f1,fc2 fp32 SGEMM -> fc3+log_softmax
// fp16 (10 mantissa bits) instead of bf16 (7): identical mma.sync throughput,
// ~8x lower quantization error (bf16 measured 1.08e-3 > 1e-3 gate).
// tcgen05 unavailable: harness PTX targets baseline sm_103 which rejects it.
// ---------------------------------------------------------------------------

#define BATCH 512
#define FS 24
#define OBJ 25
#define HID 256
#define NPAIR (BATCH * OBJ * OBJ)   // 320000

// ------------------------- scratch (static device) -------------------------
__device__ float g_c1[BATCH * FS * 40 * 40];
__device__ float g_c2[BATCH * FS * 20 * 20];
__device__ float g_c3[BATCH * FS * 10 * 10];
__device__ float g_c4[BATCH * FS * 5 * 5];
__device__ float g_stats[48];
__device__ float g_P[BATCH * OBJ * HID];
__device__ float g_Q[BATCH * OBJ * HID];
__device__ float g_R[BATCH * HID];
__device__ __half g_hA[(size_t)NPAIR * HID];          // 164MB ping (fp16)
__device__ __half g_hB[(size_t)NPAIR * HID];          // 164MB pong (fp16)
__device__ float g_hF[(size_t)NPAIR * HID];           // 327MB g4 out (fp32)
__device__ __half g_wh[3][HID * HID];                 // fp16 copies of g2w,g3w,g4w
__device__ float g_xg[BATCH * HID];
__device__ float g_xf1[BATCH * HID];
__device__ float g_xf2[BATCH * HID];

// ------------------------------ helpers ------------------------------------
__device__ __forceinline__ uint32_t smem_u32(const void* p) {
    uint32_t a;
    asm("{ .reg .u64 t; cvta.to.shared.u64 t, %1; cvt.u32.u64 %0, t; }"
        : "=r"(a) : "l"(p));
    return a;
}

__device__ __forceinline__ void ldmx4(uint32_t* r, uint32_t addr) {
    asm volatile("ldmatrix.sync.aligned.m8n8.x4.shared.b16 {%0,%1,%2,%3}, [%4];"
                 : "=r"(r[0]), "=r"(r[1]), "=r"(r[2]), "=r"(r[3]) : "r"(addr));
}

__device__ __forceinline__ void mma16816(float* d, const uint32_t* a,
                                         uint32_t b0, uint32_t b1) {
    asm volatile(
        "mma.sync.aligned.m16n8k16.row.col.f32.f16.f16.f32 "
        "{%0,%1,%2,%3}, {%4,%5,%6,%7}, {%8,%9}, {%0,%1,%2,%3};"
        : "+f"(d[0]), "+f"(d[1]), "+f"(d[2]), "+f"(d[3])
        : "r"(a[0]), "r"(a[1]), "r"(a[2]), "r"(a[3]), "r"(b0), "r"(b1));
}

// ------------------------------ conv + relu --------------------------------
__global__ void k_conv(const float* __restrict__ in, const float* __restrict__ w,
                       const float* __restrict__ bias, float* __restrict__ out,
                       int Cin, int Hin, int Win, int Hout, int Wout)
{
    int idx = blockIdx.x * blockDim.x + threadIdx.x;
    int total = BATCH * FS * Hout * Wout;
    if (idx >= total) return;
    int ow = idx % Wout; int t = idx / Wout;
    int oh = t % Hout;   t /= Hout;
    int co = t % FS;     int n = t / FS;

    float s = bias[co];
    const float* wbase = w + co * Cin * 9;
    const float* ibase = in + (size_t)n * Cin * Hin * Win;
    int ih0 = oh * 2 - 1, iw0 = ow * 2 - 1;
    for (int ci = 0; ci < Cin; ci++) {
        const float* ip = ibase + (size_t)ci * Hin * Win;
        const float* wp = wbase + ci * 9;
        #pragma unroll
        for (int kh = 0; kh < 3; kh++) {
            int ih = ih0 + kh;
            if (ih < 0 || ih >= Hin) continue;
            #pragma unroll
            for (int kw = 0; kw < 3; kw++) {
                int iw = iw0 + kw;
                if (iw < 0 || iw >= Win) continue;
                s += ip[ih * Win + iw] * wp[kh * 3 + kw];
            }
        }
    }
    out[idx] = fmaxf(s, 0.0f);
}

// ------------------------------ batchnorm ----------------------------------
__global__ void k_zero48(float* s) { if (threadIdx.x < 48) s[threadIdx.x] = 0.0f; }

__global__ void k_bnstats(const float* __restrict__ y, float* __restrict__ stats, int HW)
{
    int c = blockIdx.x;
    int per = BATCH * HW;
    float s = 0.f, s2 = 0.f;
    for (int i = blockIdx.y * blockDim.x + threadIdx.x; i < per;
         i += gridDim.y * blockDim.x) {
        int n = i / HW, hw = i - n * HW;
        float v = y[((size_t)n * FS + c) * HW + hw];
        s += v; s2 += v * v;
    }
    __shared__ float ss[256], ss2[256];
    int tid = threadIdx.x;
    ss[tid] = s; ss2[tid] = s2;
    __syncthreads();
    for (int off = 128; off > 0; off >>= 1) {
        if (tid < off) { ss[tid] += ss[tid + off]; ss2[tid] += ss2[tid + off]; }
        __syncthreads();
    }
    if (tid == 0) {
        atomicAdd(&stats[c], ss[0]);
        atomicAdd(&stats[FS + c], ss2[0]);
    }
}

__global__ void k_bnapply(float* __restrict__ y, const float* __restrict__ stats,
                          const float* __restrict__ gamma, const float* __restrict__ beta,
                          int HW, int total)
{
    int idx = blockIdx.x * blockDim.x + threadIdx.x;
    if (idx >= total) return;
    int c = (idx / HW) % FS;
    float cnt = (float)(BATCH * HW);
    float mean = stats[c] / cnt;
    float var = stats[FS + c] / cnt - mean * mean;
    float inv = gamma[c] * rsqrtf(var + 1e-5f);
    y[idx] = (y[idx] - mean) * inv + beta[c];
}

// ------------------- g1 decomposition: projections + fuse ------------------
__global__ void k_objproj(const float* __restrict__ x4, const float* __restrict__ g1w,
                          float* __restrict__ P, float* __restrict__ Q)
{
    int bo = blockIdx.x;
    int b = bo / OBJ, o = bo - b * OBJ;
    __shared__ float feat[26];
    int j = threadIdx.x;
    if (j < FS) feat[j] = x4[((size_t)b * FS + j) * OBJ + o];
    if (j == 24) feat[24] = ((o / 5) - 2) * 0.5f;
    if (j == 25) feat[25] = ((o % 5) - 2) * 0.5f;
    __syncthreads();
    const float* wr = g1w + j * 63;
    float p = 0.f, q = 0.f;
    #pragma unroll
    for (int c = 0; c < 26; c++) {
        p += wr[c] * feat[c];
        q += wr[26 + c] * feat[c];
    }
    P[(size_t)bo * HID + j] = p;
    Q[(size_t)bo * HID + j] = q;
}

__global__ void k_qproj(const float* __restrict__ qst, const float* __restrict__ g1w,
                        const float* __restrict__ g1b, float* __restrict__ R)
{
    int b = blockIdx.x, j = threadIdx.x;
    __shared__ float qs[11];
    if (j < 11) qs[j] = qst[j * BATCH + b];
    __syncthreads();
    float s = g1b[j];
    const float* wr = g1w + j * 63 + 52;
    #pragma unroll
    for (int t = 0; t < 11; t++) s += wr[t] * qs[t];
    R[b * HID + j] = s;
}

__global__ void k_g1(const float* __restrict__ P, const float* __restrict__ Q,
                     const float* __restrict__ R, __half* __restrict__ h)
{
    int row = blockIdx.x;
    int b = row / 625;
    int rem = row - b * 625;
    int a = rem / OBJ;
    int c = rem - a * OBJ;
    int j = threadIdx.x;
    float v = P[((size_t)b * OBJ + c) * HID + j]
            + Q[((size_t)b * OBJ + a) * HID + j]
            + R[b * HID + j];
    h[(size_t)row * HID + j] = __float2half_rn(fmaxf(v, 0.0f));
}

// fp32 weight [256,256] -> fp16 copy
__global__ void k_w2h(const float* __restrict__ w, __half* __restrict__ o)
{
    int i = blockIdx.x * blockDim.x + threadIdx.x;
    if (i < HID * HID) o[i] = __float2half_rn(w[i]);
}

// ----------- fp16 HMMA GEMM: C = relu(A[M,256] @ W[256,256]^T + b) ---------
// Grid (M/128, 2): blockIdx.y picks N-half. CTA 128x128, K=256 smem-resident.
// 256 threads, 8 warps tiled 4(M) x 2(N), warp tile 32x64. Padded smem rows
// (33 uint4 = 528B) -> conflict-free ldmatrix. Direct fragment stores.
#define GSM_BIAS 0
#define GSM_A    1024
#define GSM_B    (GSM_A + 128 * 528)        // A: 128 rows x 528B
#define GSM_TOT  (GSM_B + 128 * 528)        // B: 128 rows x 528B -> ~133KB

__global__ __launch_bounds__(256, 1)
void k_mmagemm(const __half* __restrict__ A,
               const __half* __restrict__ Wm,
               const float* __restrict__ bias,
               __half* __restrict__ Cb,
               float* __restrict__ Cf,
               int out32)
{
    extern __shared__ char smem[];
    float* bs = reinterpret_cast<float*>(smem + GSM_BIAS);
    uint4* sA = reinterpret_cast<uint4*>(smem + GSM_A);
    uint4* sB = reinterpret_cast<uint4*>(smem + GSM_B);
    const int tid = threadIdx.x;
    const int wid = tid >> 5;
    const int lane = tid & 31;
    const size_t bm = (size_t)blockIdx.x * 128;
    const int bn = blockIdx.y * 128;

    if (tid < 64)
        reinterpret_cast<float2*>(bs)[tid] =
            reinterpret_cast<const float2*>(bias + bn)[tid];

    // A tile: 128 rows x 32 uint4 (256 fp16)
    const uint4* Ag = reinterpret_cast<const uint4*>(A + bm * 256);
    #pragma unroll
    for (int i = 0; i < 16; i++) {
        int idx = tid + i * 256;
        int r = idx >> 5, c = idx & 31;
        sA[r * 33 + c] = Ag[idx];
    }
    // W half-tile: rows [bn, bn+128) x 32 uint4
    const uint4* Wg = reinterpret_cast<const uint4*>(Wm + (size_t)bn * 256);
    #pragma unroll
    for (int i = 0; i < 16; i++) {
        int idx = tid + i * 256;
        int r = idx >> 5, c = idx & 31;
        sB[r * 33 + c] = Wg[idx];
    }
    __syncthreads();

    const int warp_m = (wid & 3) * 32;
    const int warp_n = (wid >> 2) * 64;      // local col within the 128-half
    const uint32_t sAa = smem_u32(smem + GSM_A);
    const uint32_t sBa = smem_u32(smem + GSM_B);

    uint32_t a_addr[2], b_addr[4];
    #pragma unroll
    for (int mt = 0; mt < 2; mt++) {
        int row = warp_m + mt * 16 + (lane & 15);
        a_addr[mt] = sAa + row * 528 + (lane >> 4) * 16;
    }
    #pragma unroll
    for (int nt2 = 0; nt2 < 4; nt2++) {
        int row = warp_n + nt2 * 16 + ((lane >> 4) * 8) + (lane & 7);
        b_addr[nt2] = sBa + row * 528 + ((lane >> 3) & 1) * 16;
    }

    float acc[2][8][4];
    #pragma unroll
    for (int mt = 0; mt < 2; mt++)
        #pragma unroll
        for (int nt = 0; nt < 8; nt++)
            #pragma unroll
            for (int q = 0; q < 4; q++) acc[mt][nt][q] = 0.f;

    #pragma unroll
    for (int ks = 0; ks < 16; ks++) {
        uint32_t a[2][4], b[4][4];
        #pragma unroll
        for (int mt = 0; mt < 2; mt++) ldmx4(a[mt], a_addr[mt] + ks * 32);
        #pragma unroll
        for (int nt2 = 0; nt2 < 4; nt2++) ldmx4(b[nt2], b_addr[nt2] + ks * 32);
        #pragma unroll
        for (int mt = 0; mt < 2; mt++)
            #pragma unroll
            for (int nt = 0; nt < 8; nt++)
                mma16816(acc[mt][nt], a[mt],
                         b[nt >> 1][(nt & 1) * 2], b[nt >> 1][(nt & 1) * 2 + 1]);
    }

    // epilogue: bias + relu, store fragments directly to gmem
    #pragma unroll
    for (int mt = 0; mt < 2; mt++) {
        size_t r0 = bm + warp_m + mt * 16 + (lane >> 2);
        #pragma unroll
        for (int nt = 0; nt < 8; nt++) {
            int c0 = warp_n + nt * 8 + (lane & 3) * 2;   // local col 0..126
            float b0 = bs[c0], b1 = bs[c0 + 1];
            float v0 = fmaxf(acc[mt][nt][0] + b0, 0.f);
            float v1 = fmaxf(acc[mt][nt][1] + b1, 0.f);
            float v2 = fmaxf(acc[mt][nt][2] + b0, 0.f);
            float v3 = fmaxf(acc[mt][nt][3] + b1, 0.f);
            size_t off0 = r0 * 256 + bn + c0;
            size_t off1 = (r0 + 8) * 256 + bn + c0;
            if (out32) {
                *reinterpret_cast<float2*>(Cf + off0) = make_float2(v0, v1);
                *reinterpret_cast<float2*>(Cf + off1) = make_float2(v2, v3);
            } else {
                __half2 p01 = __floats2half2_rn(v0, v1);
                __half2 p23 = __floats2half2_rn(v2, v3);
                *reinterpret_cast<uint32_t*>(Cb + off0) =
                    *reinterpret_cast<uint32_t*>(&p01);
                *reinterpret_cast<uint32_t*>(Cb + off1) =
                    *reinterpret_cast<uint32_t*>(&p23);
            }
        }
    }
}

// ---------------- fp32 SGEMM for f-layers (small M) ------------------------
__global__ __launch_bounds__(256) void k_gemm256(const float* __restrict__ A,
    const float* __restrict__ W, const float* __restrict__ bias,
    float* __restrict__ C, int M, int doRelu)
{
    __shared__ float As[8][128];
    __shared__ float Bs[8][128];
    const int tid = threadIdx.x;
    const int bm = blockIdx.x * 128;
    const int bn = blockIdx.y * 128;
    const int tx = tid & 15;
    const int ty = tid >> 4;

    float acc[8][8];
    #pragma unroll
    for (int i = 0; i < 8; i++)
        #pragma unroll
        for (int j = 0; j < 8; j++) acc[i][j] = 0.f;

    const int lrow = tid >> 1;
    const int lk = (tid & 1) * 4;
    const float* Ag = A + (size_t)(bm + lrow) * 256 + lk;
    const float* Wg = W + (size_t)(bn + lrow) * 256 + lk;

    for (int k0 = 0; k0 < 256; k0 += 8) {
        float4 av = *reinterpret_cast<const float4*>(Ag + k0);
        float4 wv = *reinterpret_cast<const float4*>(Wg + k0);
        As[lk + 0][lrow] = av.x; As[lk + 1][lrow] = av.y;
        As[lk + 2][lrow] = av.z; As[lk + 3][lrow] = av.w;
        Bs[lk + 0][lrow] = wv.x; Bs[lk + 1][lrow] = wv.y;
        Bs[lk + 2][lrow] = wv.z; Bs[lk + 3][lrow] = wv.w;
        __syncthreads();
        #pragma unroll
        for (int kk = 0; kk < 8; kk++) {
            float a[8], b[8];
            *reinterpret_cast<float4*>(&a[0]) = *reinterpret_cast<const float4*>(&As[kk][ty * 8]);
            *reinterpret_cast<float4*>(&a[4]) = *reinterpret_cast<const float4*>(&As[kk][ty * 8 + 4]);
            *reinterpret_cast<float4*>(&b[0]) = *reinterpret_cast<const float4*>(&Bs[kk][tx * 8]);
            *reinterpret_cast<float4*>(&b[4]) = *reinterpret_cast<const float4*>(&Bs[kk][tx * 8 + 4]);
            #pragma unroll
            for (int i = 0; i < 8; i++)
                #pragma unroll
                for (int j = 0; j < 8; j++)
                    acc[i][j] += a[i] * b[j];
        }
        __syncthreads();
    }

    #pragma unroll
    for (int i = 0; i < 8; i++) {
        size_t row = (size_t)(bm + ty * 8 + i);
        #pragma unroll
        for (int j = 0; j < 8; j += 4) {
            int col = bn + tx * 8 + j;
            float4 v;
            v.x = acc[i][j + 0] + bias[col + 0];
            v.y = acc[i][j + 1] + bias[col + 1];
            v.z = acc[i][j + 2] + bias[col + 2];
            v.w = acc[i][j + 3] + bias[col + 3];
            if (doRelu) {
                v.x = fmaxf(v.x, 0.f); v.y = fmaxf(v.y, 0.f);
                v.z = fmaxf(v.z, 0.f); v.w = fmaxf(v.w, 0.f);
            }
            *reinterpret_cast<float4*>(&C[row * 256 + col]) = v;
        }
    }
}

// ---------------------------- pair sum (fp32 in) ---------------------------
__global__ void k_pairsum(const float* __restrict__ h, float* __restrict__ xg)
{
    int b = blockIdx.x, j = threadIdx.x;
    const float* base = h + (size_t)b * 625 * HID + j;
    float s0 = 0, s1 = 0, s2 = 0, s3 = 0;
    int p = 0;
    for (; p + 4 <= 624; p += 4) {
        s0 += base[(size_t)(p + 0) * HID];
        s1 += base[(size_t)(p + 1) * HID];
        s2 += base[(size_t)(p + 2) * HID];
        s3 += base[(size_t)(p + 3) * HID];
    }
    float s = s0 + s1 + s2 + s3;
    for (; p < 625; p++) s += base[(size_t)p * HID];
    xg[b * HID + j] = s;
}

// -------------------- fc3 (256->10) + log_softmax --------------------------
__global__ void k_final(const float* __restrict__ xf, const float* __restrict__ w,
                        const float* __restrict__ bias, float* __restrict__ out)
{
    int b = blockIdx.x;
    __shared__ float xs[HID];
    __shared__ float logits[10];
    xs[threadIdx.x] = xf[b * HID + threadIdx.x];
    __syncthreads();
    if (threadIdx.x < 10) {
        float s = bias[threadIdx.x];
        const float* wr = w + threadIdx.x * HID;
        for (int c = 0; c < HID; c++) s += wr[c] * xs[c];
        logits[threadIdx.x] = s;
    }
    __syncthreads();
    if (threadIdx.x == 0) {
        float mx = -1e30f;
        for (int n = 0; n < 10; n++) mx = fmaxf(mx, logits[n]);
        float se = 0.f;
        for (int n = 0; n < 10; n++) se += expf(logits[n] - mx);
        float lse = logf(se) + mx;
        for (int n = 0; n < 10; n++) out[b * 10 + n] = logits[n] - lse;
    }
}

// ---------------------------------------------------------------------------
static void* sym(const void* devSymbol)
{
    void* p = nullptr;
    cudaGetSymbolAddress(&p, devSymbol);
    return p;
}

extern "C" void kernel_launch(void* const* d_in, const int* in_sizes, int n_in,
                              void* d_out, int out_size)
{
    const float* img  = (const float*)d_in[0];
    const float* qst  = (const float*)d_in[1];
    const float* cw[4] = { (const float*)d_in[2],  (const float*)d_in[6],
                           (const float*)d_in[10], (const float*)d_in[14] };
    const float* cb[4] = { (const float*)d_in[3],  (const float*)d_in[7],
                           (const float*)d_in[11], (const float*)d_in[15] };
    const float* bg[4] = { (const float*)d_in[4],  (const float*)d_in[8],
                           (const float*)d_in[12], (const float*)d_in[16] };
    const float* bb[4] = { (const float*)d_in[5],  (const float*)d_in[9],
                           (const float*)d_in[13], (const float*)d_in[17] };
    const float* g1w = (const float*)d_in[18]; const float* g1b = (const float*)d_in[19];
    const float* g2w = (const float*)d_in[20]; const float* g2b = (const float*)d_in[21];
    const float* g3w = (const float*)d_in[22]; const float* g3b = (const float*)d_in[23];
    const float* g4w = (const float*)d_in[24]; const float* g4b = (const float*)d_in[25];
    const float* f1w = (const float*)d_in[26]; const float* f1b = (const float*)d_in[27];
    const float* fc2w = (const float*)d_in[28]; const float* fc2b = (const float*)d_in[29];
    const float* fc3w = (const float*)d_in[30]; const float* fc3b = (const float*)d_in[31];

    float* c1 = (float*)sym(g_c1); float* c2 = (float*)sym(g_c2);
    float* c3 = (float*)sym(g_c3); float* c4 = (float*)sym(g_c4);
    float* stats = (float*)sym(g_stats);
    float* P = (float*)sym(g_P); float* Q = (float*)sym(g_Q); float* R = (float*)sym(g_R);
    __half* hA = (__half*)sym(g_hA);
    __half* hB = (__half*)sym(g_hB);
    float* hF = (float*)sym(g_hF);
    __half* wh = (__half*)sym(g_wh);
    float* xg = (float*)sym(g_xg); float* xf1 = (float*)sym(g_xf1); float* xf2 = (float*)sym(g_xf2);
    float* out = (float*)d_out;

    cudaFuncSetAttribute(k_mmagemm, cudaFuncAttributeMaxDynamicSharedMemorySize, GSM_TOT);

    struct { const float* in; float* out; int Cin, Hin, Hout; } L[4] = {
        { img, c1, 3, 80, 40 },
        { c1,  c2, FS, 40, 20 },
        { c2,  c3, FS, 20, 10 },
        { c3,  c4, FS, 10, 5 },
    };

    for (int l = 0; l < 4; l++) {
        int Hout = L[l].Hout, HW = Hout * Hout;
        int total = BATCH * FS * HW;
        k_conv<<<(total + 255) / 256, 256>>>(L[l].in, cw[l], cb[l], L[l].out,
                                             L[l].Cin, L[l].Hin, L[l].Hin, Hout, Hout);
        k_zero48<<<1, 64>>>(stats);
        k_bnstats<<<dim3(FS, 64), 256>>>(L[l].out, stats, HW);
        k_bnapply<<<(total + 255) / 256, 256>>>(L[l].out, stats, bg[l], bb[l], HW, total);
    }

    // fp16 weight copies for HMMA GEMMs
    k_w2h<<<(HID * HID + 255) / 256, 256>>>(g2w, wh);
    k_w2h<<<(HID * HID + 255) / 256, 256>>>(g3w, wh + HID * HID);
    k_w2h<<<(HID * HID + 255) / 256, 256>>>(g4w, wh + 2 * HID * HID);

    // g1 decomposition (fp16 output)
    k_objproj<<<BATCH * OBJ, HID>>>(c4, g1w, P, Q);
    k_qproj<<<BATCH, HID>>>(qst, g1w, g1b, R);
    k_g1<<<NPAIR, HID>>>(P, Q, R, hA);

    // g2..g4 tensor-core GEMMs (g4 writes fp32)
    dim3 gg(NPAIR / 128, 2);
    k_mmagemm<<<gg, 256, GSM_TOT>>>(hA, wh,                 g2b, hB, nullptr, 0);
    k_mmagemm<<<gg, 256, GSM_TOT>>>(hB, wh + HID * HID,     g3b, hA, nullptr, 0);
    k_mmagemm<<<gg, 256, GSM_TOT>>>(hA, wh + 2 * HID * HID, g4b, nullptr, hF, 1);

    // sum over 625 pairs
    k_pairsum<<<BATCH, HID>>>(hF, xg);

    // f layers (fp32)
    dim3 gsmall(BATCH / 128, 2);
    k_gemm256<<<gsmall, 256>>>(xg, f1w, f1b, xf1, BATCH, 1);
    k_gemm256<<<gsmall, 256>>>(xf1, fc2w, fc2b, xf2, BATCH, 1);

    // fc3 + log_softmax
    k_final<<<BATCH, HID>>>(xf2, fc3w, fc3b, out);
}